// round 15
// baseline (speedup 1.0000x reference)
#include <cuda_runtime.h>
#include <cuda_bf16.h>
#include <cstdint>

#define MAX_N 100000
#define MAX_E 1000000
#define D 64
#define TILE 64
#define PITCH 36

// Scratch (device globals: sanctioned alternative to cudaMalloc).
// INVARIANT: g_cnt is all-zero at kernel_launch entry (zero-initialized at
// module load; gather_kernel re-zeroes it after use every call).
__device__ float g_hs[MAX_N * D];    // hs = dinv[n] * (x @ W^T)[n]  (prescaled)
__device__ float g_dinv[MAX_N];
__device__ int   g_cnt[MAX_N];
__device__ int   g_start[MAX_N];
__device__ int   g_cursor[MAX_N];
__device__ int   g_ebuf[MAX_E];
__device__ int   g_bsum[128];

// ---------------------------------------------------------------------------
// 1) degree histogram: 4 edges per thread (int4) for MLP on the RED chain
// ---------------------------------------------------------------------------
__global__ void deg_acc_kernel(const int* __restrict__ ei, int E) {
    int e4 = (blockIdx.x * blockDim.x + threadIdx.x) * 4;
    if (e4 < E) {
        int4 d4 = *(const int4*)(ei + E + e4);
        asm volatile("red.global.add.s32 [%0], %1;" :: "l"(&g_cnt[d4.x]), "r"(1) : "memory");
        asm volatile("red.global.add.s32 [%0], %1;" :: "l"(&g_cnt[d4.y]), "r"(1) : "memory");
        asm volatile("red.global.add.s32 [%0], %1;" :: "l"(&g_cnt[d4.z]), "r"(1) : "memory");
        asm volatile("red.global.add.s32 [%0], %1;" :: "l"(&g_cnt[d4.w]), "r"(1) : "memory");
    }
}

// ---------------------------------------------------------------------------
// 2) level-1 scan
// ---------------------------------------------------------------------------
__global__ __launch_bounds__(1024)
void scan1_kernel(int N) {
    __shared__ int wsum[32];
    int i = blockIdx.x * 1024 + threadIdx.x;
    int lane = threadIdx.x & 31, wid = threadIdx.x >> 5;
    int v = (i < N) ? g_cnt[i] : 0;
    int val = v;
#pragma unroll
    for (int off = 1; off < 32; off <<= 1) {
        int t = __shfl_up_sync(0xffffffffu, val, off);
        if (lane >= off) val += t;
    }
    if (lane == 31) wsum[wid] = val;
    __syncthreads();
    if (wid == 0) {
        int w = wsum[lane];
#pragma unroll
        for (int off = 1; off < 32; off <<= 1) {
            int t = __shfl_up_sync(0xffffffffu, w, off);
            if (lane >= off) w += t;
        }
        wsum[lane] = w;
    }
    __syncthreads();
    int incl = val + (wid > 0 ? wsum[wid - 1] : 0);
    if (i < N) g_start[i] = incl - v;
    if (threadIdx.x == 1023) g_bsum[blockIdx.x] = incl;
}

// 3) fused level-2 scan + finalize (start/cursor/dinv)
__global__ __launch_bounds__(256)
void scan23_kernel(int N, int nb) {
    __shared__ int pre[128];
    int tid = threadIdx.x;
    if (tid < 32) {
        int run = 0;
        for (int b = 0; b < nb; b += 32) {
            int idx = b + tid;
            int v = (idx < nb) ? g_bsum[idx] : 0;
            int val = v;
#pragma unroll
            for (int off = 1; off < 32; off <<= 1) {
                int t = __shfl_up_sync(0xffffffffu, val, off);
                if (tid >= off) val += t;
            }
            if (idx < 128) pre[idx] = run + val - v;
            run += __shfl_sync(0xffffffffu, val, 31);
        }
    }
    __syncthreads();
    int i = blockIdx.x * 256 + tid;
    if (i < N) {
        int s = g_start[i] + pre[i >> 10];
        g_start[i]  = s;
        g_cursor[i] = s;
        g_dinv[i]   = rsqrtf(1.0f + (float)g_cnt[i]);
    }
}

// ---------------------------------------------------------------------------
// helpers for the mma gemm
// ---------------------------------------------------------------------------
__device__ __forceinline__ uint32_t pack_bf(float a, float b) {
    __nv_bfloat162 p = __floats2bfloat162_rn(a, b);
    return *(uint32_t*)&p;
}

#define MMA_BF16(c, a0, a1, a2, a3, b0, b1)                                   \
    asm volatile(                                                             \
        "mma.sync.aligned.m16n8k16.row.col.f32.bf16.bf16.f32 "                \
        "{%0,%1,%2,%3}, {%4,%5,%6,%7}, {%8,%9}, {%0,%1,%2,%3};"               \
        : "+f"((c)[0]), "+f"((c)[1]), "+f"((c)[2]), "+f"((c)[3])              \
        : "r"(a0), "r"(a1), "r"(a2), "r"(a3), "r"(b0), "r"(b1))

// ---------------------------------------------------------------------------
// 4) FUSED gemm+fill: blocks [0,Gg) run the mma gemm (hs = dinv * x@W^T);
//    blocks [Gg, Gg+Gf) run the bucket fill (4 edges/thread, int4 loads).
//    The two are independent (both depend only on scan23) -> they overlap
//    inside one launch instead of running sequentially.
// ---------------------------------------------------------------------------
__global__ __launch_bounds__(256)
void gemm_fill_kernel(const float* __restrict__ x,
                      const float* __restrict__ W,
                      const int* __restrict__ ei,
                      int N, int E, int Gg) {
    __shared__ uint32_t Ah[TILE * PITCH], Al[TILE * PITCH];
    __shared__ uint32_t Bh[D * PITCH],   Bl[D * PITCH];

    int tid = threadIdx.x;

    if ((int)blockIdx.x >= Gg) {
        // ---- fill branch: 4 edges per thread ----
        int e4 = ((blockIdx.x - Gg) * 256 + tid) * 4;
        if (e4 < E) {
            int4 s4 = *(const int4*)(ei + e4);
            int4 d4 = *(const int4*)(ei + E + e4);
            int p0 = atomicAdd(&g_cursor[d4.x], 1);
            int p1 = atomicAdd(&g_cursor[d4.y], 1);
            int p2 = atomicAdd(&g_cursor[d4.z], 1);
            int p3 = atomicAdd(&g_cursor[d4.w], 1);
            g_ebuf[p0] = s4.x;
            g_ebuf[p1] = s4.y;
            g_ebuf[p2] = s4.z;
            g_ebuf[p3] = s4.w;
        }
        return;
    }

    // ---- gemm branch: 8 warps, warp = 16 rows x 32 cols ----
    int base = blockIdx.x * TILE;
    int rows = N - base; if (rows > TILE) rows = TILE;

    const float4* xg = (const float4*)(x + (size_t)base * D);
    for (int t = tid; t < rows * 16; t += 256) {
        int r = t >> 4, j = t & 15;
        float4 v = xg[t];
        float hx = __bfloat162float(__float2bfloat16(v.x));
        float hy = __bfloat162float(__float2bfloat16(v.y));
        float hz = __bfloat162float(__float2bfloat16(v.z));
        float hw = __bfloat162float(__float2bfloat16(v.w));
        Ah[r * PITCH + 2 * j]     = pack_bf(v.x, v.y);
        Ah[r * PITCH + 2 * j + 1] = pack_bf(v.z, v.w);
        Al[r * PITCH + 2 * j]     = pack_bf(v.x - hx, v.y - hy);
        Al[r * PITCH + 2 * j + 1] = pack_bf(v.z - hz, v.w - hw);
    }
    const float4* wg = (const float4*)W;
    for (int t = tid; t < D * 16; t += 256) {
        int o = t >> 4, j = t & 15;
        float4 v = wg[t];
        float hx = __bfloat162float(__float2bfloat16(v.x));
        float hy = __bfloat162float(__float2bfloat16(v.y));
        float hz = __bfloat162float(__float2bfloat16(v.z));
        float hw = __bfloat162float(__float2bfloat16(v.w));
        Bh[o * PITCH + 2 * j]     = pack_bf(v.x, v.y);
        Bh[o * PITCH + 2 * j + 1] = pack_bf(v.z, v.w);
        Bl[o * PITCH + 2 * j]     = pack_bf(v.x - hx, v.y - hy);
        Bl[o * PITCH + 2 * j + 1] = pack_bf(v.z - hz, v.w - hw);
    }
    __syncthreads();

    int lane = tid & 31;
    int w    = tid >> 5;
    int g    = lane >> 2;
    int kq   = lane & 3;
    int rb   = (w & 3) * 16;       // row base within tile
    int nb4  = (w >> 2) * 4;       // n-tile base: tiles nb4..nb4+3 (8 cols each)

    float c[4][4];
#pragma unroll
    for (int t = 0; t < 4; t++)
#pragma unroll
        for (int i = 0; i < 4; i++) c[t][i] = 0.f;

#pragma unroll
    for (int s = 0; s < 4; s++) {
        int ko = s * 8 + kq;
        uint32_t ah0 = Ah[(rb + g) * PITCH + ko];
        uint32_t ah1 = Ah[(rb + g + 8) * PITCH + ko];
        uint32_t ah2 = Ah[(rb + g) * PITCH + ko + 4];
        uint32_t ah3 = Ah[(rb + g + 8) * PITCH + ko + 4];
        uint32_t al0 = Al[(rb + g) * PITCH + ko];
        uint32_t al1 = Al[(rb + g + 8) * PITCH + ko];
        uint32_t al2 = Al[(rb + g) * PITCH + ko + 4];
        uint32_t al3 = Al[(rb + g + 8) * PITCH + ko + 4];
#pragma unroll
        for (int t = 0; t < 4; t++) {
            int nr = (nb4 + t) * 8 + g;
            uint32_t bh0 = Bh[nr * PITCH + ko];
            uint32_t bh1 = Bh[nr * PITCH + ko + 4];
            uint32_t bl0 = Bl[nr * PITCH + ko];
            uint32_t bl1 = Bl[nr * PITCH + ko + 4];
            MMA_BF16(c[t], ah0, ah1, ah2, ah3, bh0, bh1);
            MMA_BF16(c[t], ah0, ah1, ah2, ah3, bl0, bl1);
            MMA_BF16(c[t], al0, al1, al2, al3, bh0, bh1);
        }
    }

    int r0 = base + rb + g;
    int r1 = r0 + 8;
    bool v0 = (r0 < N), v1 = (r1 < N);
    float dv0 = v0 ? g_dinv[r0] : 0.f;
    float dv1 = v1 ? g_dinv[r1] : 0.f;

    float2* h2 = (float2*)g_hs;
#pragma unroll
    for (int t = 0; t < 4; t++) {
        int col2 = (nb4 + t) * 4 + kq;
        if (v0) h2[(size_t)r0 * 32 + col2] = make_float2(dv0 * c[t][0], dv0 * c[t][1]);
        if (v1) h2[(size_t)r1 * 32 + col2] = make_float2(dv1 * c[t][2], dv1 * c[t][3]);
    }
}

// ---------------------------------------------------------------------------
// 5) Gather: one warp per node (proven R13/R14). Restores g_cnt invariant.
// ---------------------------------------------------------------------------
__global__ __launch_bounds__(256)
void gather_kernel(const float* __restrict__ bias,
                   float* __restrict__ out, int N) {
    int warp = (blockIdx.x * 256 + threadIdx.x) >> 5;
    int lane = threadIdx.x & 31;
    if (warp >= N) return;
    int n = warp;

    int start = g_start[n];
    int cnt   = g_cnt[n];

    const float2* hs2 = (const float2*)g_hs;

    float2 a0 = hs2[(size_t)n * 32 + lane];
    float2 a1 = make_float2(0.f, 0.f);
    float2 a2 = make_float2(0.f, 0.f);
    float2 a3 = make_float2(0.f, 0.f);

    int i = 0;
    while (i < cnt) {
        int bc = cnt - i; if (bc > 32) bc = 32;
        int v = (lane < bc) ? g_ebuf[start + i + lane] : 0;
        int j = 0;
        for (; j + 4 <= bc; j += 4) {
            int s0 = __shfl_sync(0xffffffffu, v, j);
            int s1 = __shfl_sync(0xffffffffu, v, j + 1);
            int s2 = __shfl_sync(0xffffffffu, v, j + 2);
            int s3 = __shfl_sync(0xffffffffu, v, j + 3);
            float2 x0 = hs2[(size_t)s0 * 32 + lane];
            float2 x1 = hs2[(size_t)s1 * 32 + lane];
            float2 x2 = hs2[(size_t)s2 * 32 + lane];
            float2 x3 = hs2[(size_t)s3 * 32 + lane];
            a0.x += x0.x; a0.y += x0.y;
            a1.x += x1.x; a1.y += x1.y;
            a2.x += x2.x; a2.y += x2.y;
            a3.x += x3.x; a3.y += x3.y;
        }
        for (; j < bc; j++) {
            int s0 = __shfl_sync(0xffffffffu, v, j);
            float2 x0 = hs2[(size_t)s0 * 32 + lane];
            a0.x += x0.x; a0.y += x0.y;
        }
        i += bc;
    }
    a0.x += (a1.x + a2.x) + a3.x;
    a0.y += (a1.y + a2.y) + a3.y;

    float dn = g_dinv[n];
    float2 bb = ((const float2*)bias)[lane];
    float2 o;
    o.x = fmaf(dn, a0.x, bb.x);
    o.y = fmaf(dn, a0.y, bb.y);
    ((float2*)out)[(size_t)n * 32 + lane] = o;

    if (lane == 0) g_cnt[n] = 0;   // restore invariant for next call
}

// ---------------------------------------------------------------------------
extern "C" void kernel_launch(void* const* d_in, const int* in_sizes, int n_in,
                              void* d_out, int out_size) {
    const float* x  = (const float*)d_in[0];
    const int*   ei = (const int*)d_in[1];
    const float* W  = (const float*)d_in[2];
    const float* b  = (const float*)d_in[3];
    float*       out = (float*)d_out;

    int N = in_sizes[0] / D;   // 100000
    int E = in_sizes[1] / 2;   // 1000000
    int nb = (N + 1023) / 1024;

    int e_threads = (E + 3) / 4;
    int Gf = (e_threads + 255) / 256;        // 977 fill blocks
    int Gg = (N + TILE - 1) / TILE;          // 1563 gemm blocks

    deg_acc_kernel<<<Gf, 256>>>(ei, E);
    scan1_kernel<<<nb, 1024>>>(N);
    scan23_kernel<<<(N + 255) / 256, 256>>>(N, nb);
    gemm_fill_kernel<<<Gg + Gf, 256>>>(x, W, ei, N, E, Gg);
    gather_kernel<<<(N * 32 + 255) / 256, 256>>>(b, out, N);
}

// round 16
// speedup vs baseline: 1.0047x; 1.0047x over previous
#include <cuda_runtime.h>
#include <cuda_bf16.h>
#include <cstdint>

#define MAX_N 100000
#define MAX_E 1000000
#define D 64
#define TILE 64
#define PITCH 36

// Scratch (device globals: sanctioned alternative to cudaMalloc).
// INVARIANT: g_cnt is all-zero at kernel_launch entry (zero-initialized at
// module load; gather_kernel re-zeroes it after use every call).
__device__ float g_hs[MAX_N * D];    // hs = dinv[n] * (x @ W^T)[n]  (prescaled)
__device__ float g_dinv[MAX_N];
__device__ int   g_cnt[MAX_N];
__device__ int   g_start[MAX_N];
__device__ int   g_cursor[MAX_N];
__device__ int   g_ebuf[MAX_E];
__device__ int   g_bsum[128];

// ---------------------------------------------------------------------------
// 1) degree histogram: 4 edges per thread (int4) for MLP on the RED chain
// ---------------------------------------------------------------------------
__global__ void deg_acc_kernel(const int* __restrict__ ei, int E) {
    int e4 = (blockIdx.x * blockDim.x + threadIdx.x) * 4;
    if (e4 < E) {
        int4 d4 = *(const int4*)(ei + E + e4);
        asm volatile("red.global.add.s32 [%0], %1;" :: "l"(&g_cnt[d4.x]), "r"(1) : "memory");
        asm volatile("red.global.add.s32 [%0], %1;" :: "l"(&g_cnt[d4.y]), "r"(1) : "memory");
        asm volatile("red.global.add.s32 [%0], %1;" :: "l"(&g_cnt[d4.z]), "r"(1) : "memory");
        asm volatile("red.global.add.s32 [%0], %1;" :: "l"(&g_cnt[d4.w]), "r"(1) : "memory");
    }
}

// ---------------------------------------------------------------------------
// 2) level-1 scan
// ---------------------------------------------------------------------------
__global__ __launch_bounds__(1024)
void scan1_kernel(int N) {
    __shared__ int wsum[32];
    int i = blockIdx.x * 1024 + threadIdx.x;
    int lane = threadIdx.x & 31, wid = threadIdx.x >> 5;
    int v = (i < N) ? g_cnt[i] : 0;
    int val = v;
#pragma unroll
    for (int off = 1; off < 32; off <<= 1) {
        int t = __shfl_up_sync(0xffffffffu, val, off);
        if (lane >= off) val += t;
    }
    if (lane == 31) wsum[wid] = val;
    __syncthreads();
    if (wid == 0) {
        int w = wsum[lane];
#pragma unroll
        for (int off = 1; off < 32; off <<= 1) {
            int t = __shfl_up_sync(0xffffffffu, w, off);
            if (lane >= off) w += t;
        }
        wsum[lane] = w;
    }
    __syncthreads();
    int incl = val + (wid > 0 ? wsum[wid - 1] : 0);
    if (i < N) g_start[i] = incl - v;
    if (threadIdx.x == 1023) g_bsum[blockIdx.x] = incl;
}

// 3) fused level-2 scan + finalize (start/cursor/dinv)
__global__ __launch_bounds__(256)
void scan23_kernel(int N, int nb) {
    __shared__ int pre[128];
    int tid = threadIdx.x;
    if (tid < 32) {
        int run = 0;
        for (int b = 0; b < nb; b += 32) {
            int idx = b + tid;
            int v = (idx < nb) ? g_bsum[idx] : 0;
            int val = v;
#pragma unroll
            for (int off = 1; off < 32; off <<= 1) {
                int t = __shfl_up_sync(0xffffffffu, val, off);
                if (tid >= off) val += t;
            }
            if (idx < 128) pre[idx] = run + val - v;
            run += __shfl_sync(0xffffffffu, val, 31);
        }
    }
    __syncthreads();
    int i = blockIdx.x * 256 + tid;
    if (i < N) {
        int s = g_start[i] + pre[i >> 10];
        g_start[i]  = s;
        g_cursor[i] = s;
        g_dinv[i]   = rsqrtf(1.0f + (float)g_cnt[i]);
    }
}

// ---------------------------------------------------------------------------
// 4) bucket fill: 4 edges per thread (int4 loads, 4 independent atomic chains)
// ---------------------------------------------------------------------------
__global__ void fill_kernel(const int* __restrict__ ei, int E) {
    int e4 = (blockIdx.x * blockDim.x + threadIdx.x) * 4;
    if (e4 < E) {
        int4 s4 = *(const int4*)(ei + e4);
        int4 d4 = *(const int4*)(ei + E + e4);
        int p0 = atomicAdd(&g_cursor[d4.x], 1);
        int p1 = atomicAdd(&g_cursor[d4.y], 1);
        int p2 = atomicAdd(&g_cursor[d4.z], 1);
        int p3 = atomicAdd(&g_cursor[d4.w], 1);
        g_ebuf[p0] = s4.x;
        g_ebuf[p1] = s4.y;
        g_ebuf[p2] = s4.z;
        g_ebuf[p3] = s4.w;
    }
}

// ---------------------------------------------------------------------------
// Tensor-core GEMM via mma.sync (proven R12/R13/R14): hs = dinv * (x @ W^T)
// ---------------------------------------------------------------------------
__device__ __forceinline__ uint32_t pack_bf(float a, float b) {
    __nv_bfloat162 p = __floats2bfloat162_rn(a, b);
    return *(uint32_t*)&p;
}

#define MMA_BF16(c, a0, a1, a2, a3, b0, b1)                                   \
    asm volatile(                                                             \
        "mma.sync.aligned.m16n8k16.row.col.f32.bf16.bf16.f32 "                \
        "{%0,%1,%2,%3}, {%4,%5,%6,%7}, {%8,%9}, {%0,%1,%2,%3};"               \
        : "+f"((c)[0]), "+f"((c)[1]), "+f"((c)[2]), "+f"((c)[3])              \
        : "r"(a0), "r"(a1), "r"(a2), "r"(a3), "r"(b0), "r"(b1))

__global__ __launch_bounds__(128)
void gemm_mma_kernel(const float* __restrict__ x,
                     const float* __restrict__ W, int N) {
    __shared__ uint32_t Ah[TILE * PITCH], Al[TILE * PITCH];
    __shared__ uint32_t Bh[D * PITCH],   Bl[D * PITCH];

    int tid = threadIdx.x;
    int base = blockIdx.x * TILE;
    int rows = N - base; if (rows > TILE) rows = TILE;

    const float4* xg = (const float4*)(x + (size_t)base * D);
    for (int t = tid; t < rows * 16; t += 128) {
        int r = t >> 4, j = t & 15;
        float4 v = xg[t];
        float hx = __bfloat162float(__float2bfloat16(v.x));
        float hy = __bfloat162float(__float2bfloat16(v.y));
        float hz = __bfloat162float(__float2bfloat16(v.z));
        float hw = __bfloat162float(__float2bfloat16(v.w));
        Ah[r * PITCH + 2 * j]     = pack_bf(v.x, v.y);
        Ah[r * PITCH + 2 * j + 1] = pack_bf(v.z, v.w);
        Al[r * PITCH + 2 * j]     = pack_bf(v.x - hx, v.y - hy);
        Al[r * PITCH + 2 * j + 1] = pack_bf(v.z - hz, v.w - hw);
    }
    const float4* wg = (const float4*)W;
    for (int t = tid; t < D * 16; t += 128) {
        int o = t >> 4, j = t & 15;
        float4 v = wg[t];
        float hx = __bfloat162float(__float2bfloat16(v.x));
        float hy = __bfloat162float(__float2bfloat16(v.y));
        float hz = __bfloat162float(__float2bfloat16(v.z));
        float hw = __bfloat162float(__float2bfloat16(v.w));
        Bh[o * PITCH + 2 * j]     = pack_bf(v.x, v.y);
        Bh[o * PITCH + 2 * j + 1] = pack_bf(v.z, v.w);
        Bl[o * PITCH + 2 * j]     = pack_bf(v.x - hx, v.y - hy);
        Bl[o * PITCH + 2 * j + 1] = pack_bf(v.z - hz, v.w - hw);
    }
    __syncthreads();

    int lane = tid & 31;
    int w    = tid >> 5;
    int g    = lane >> 2;
    int kq   = lane & 3;
    int rb   = w * 16;

    float c[8][4];
#pragma unroll
    for (int t = 0; t < 8; t++)
#pragma unroll
        for (int i = 0; i < 4; i++) c[t][i] = 0.f;

#pragma unroll
    for (int s = 0; s < 4; s++) {
        int ko = s * 8 + kq;
        uint32_t ah0 = Ah[(rb + g) * PITCH + ko];
        uint32_t ah1 = Ah[(rb + g + 8) * PITCH + ko];
        uint32_t ah2 = Ah[(rb + g) * PITCH + ko + 4];
        uint32_t ah3 = Ah[(rb + g + 8) * PITCH + ko + 4];
        uint32_t al0 = Al[(rb + g) * PITCH + ko];
        uint32_t al1 = Al[(rb + g + 8) * PITCH + ko];
        uint32_t al2 = Al[(rb + g) * PITCH + ko + 4];
        uint32_t al3 = Al[(rb + g + 8) * PITCH + ko + 4];
#pragma unroll
        for (int t = 0; t < 8; t++) {
            int nr = t * 8 + g;
            uint32_t bh0 = Bh[nr * PITCH + ko];
            uint32_t bh1 = Bh[nr * PITCH + ko + 4];
            uint32_t bl0 = Bl[nr * PITCH + ko];
            uint32_t bl1 = Bl[nr * PITCH + ko + 4];
            MMA_BF16(c[t], ah0, ah1, ah2, ah3, bh0, bh1);
            MMA_BF16(c[t], ah0, ah1, ah2, ah3, bl0, bl1);
            MMA_BF16(c[t], al0, al1, al2, al3, bh0, bh1);
        }
    }

    int r0 = base + rb + g;
    int r1 = r0 + 8;
    bool v0 = (r0 < N), v1 = (r1 < N);
    float dv0 = v0 ? g_dinv[r0] : 0.f;
    float dv1 = v1 ? g_dinv[r1] : 0.f;

    float2* h2 = (float2*)g_hs;
#pragma unroll
    for (int t = 0; t < 8; t++) {
        int col2 = t * 4 + kq;
        if (v0) h2[(size_t)r0 * 32 + col2] = make_float2(dv0 * c[t][0], dv0 * c[t][1]);
        if (v1) h2[(size_t)r1 * 32 + col2] = make_float2(dv1 * c[t][2], dv1 * c[t][3]);
    }
}

// ---------------------------------------------------------------------------
// Gather: one warp per node (proven R13/R14). Restores g_cnt invariant.
// ---------------------------------------------------------------------------
__global__ __launch_bounds__(256)
void gather_kernel(const float* __restrict__ bias,
                   float* __restrict__ out, int N) {
    int warp = (blockIdx.x * 256 + threadIdx.x) >> 5;
    int lane = threadIdx.x & 31;
    if (warp >= N) return;
    int n = warp;

    int start = g_start[n];
    int cnt   = g_cnt[n];

    const float2* hs2 = (const float2*)g_hs;

    float2 a0 = hs2[(size_t)n * 32 + lane];
    float2 a1 = make_float2(0.f, 0.f);
    float2 a2 = make_float2(0.f, 0.f);
    float2 a3 = make_float2(0.f, 0.f);

    int i = 0;
    while (i < cnt) {
        int bc = cnt - i; if (bc > 32) bc = 32;
        int v = (lane < bc) ? g_ebuf[start + i + lane] : 0;
        int j = 0;
        for (; j + 4 <= bc; j += 4) {
            int s0 = __shfl_sync(0xffffffffu, v, j);
            int s1 = __shfl_sync(0xffffffffu, v, j + 1);
            int s2 = __shfl_sync(0xffffffffu, v, j + 2);
            int s3 = __shfl_sync(0xffffffffu, v, j + 3);
            float2 x0 = hs2[(size_t)s0 * 32 + lane];
            float2 x1 = hs2[(size_t)s1 * 32 + lane];
            float2 x2 = hs2[(size_t)s2 * 32 + lane];
            float2 x3 = hs2[(size_t)s3 * 32 + lane];
            a0.x += x0.x; a0.y += x0.y;
            a1.x += x1.x; a1.y += x1.y;
            a2.x += x2.x; a2.y += x2.y;
            a3.x += x3.x; a3.y += x3.y;
        }
        for (; j < bc; j++) {
            int s0 = __shfl_sync(0xffffffffu, v, j);
            float2 x0 = hs2[(size_t)s0 * 32 + lane];
            a0.x += x0.x; a0.y += x0.y;
        }
        i += bc;
    }
    a0.x += (a1.x + a2.x) + a3.x;
    a0.y += (a1.y + a2.y) + a3.y;

    float dn = g_dinv[n];
    float2 bb = ((const float2*)bias)[lane];
    float2 o;
    o.x = fmaf(dn, a0.x, bb.x);
    o.y = fmaf(dn, a0.y, bb.y);
    ((float2*)out)[(size_t)n * 32 + lane] = o;

    if (lane == 0) g_cnt[n] = 0;   // restore invariant for next call
}

// ---------------------------------------------------------------------------
extern "C" void kernel_launch(void* const* d_in, const int* in_sizes, int n_in,
                              void* d_out, int out_size) {
    const float* x  = (const float*)d_in[0];
    const int*   ei = (const int*)d_in[1];
    const float* W  = (const float*)d_in[2];
    const float* b  = (const float*)d_in[3];
    float*       out = (float*)d_out;

    int N = in_sizes[0] / D;   // 100000
    int E = in_sizes[1] / 2;   // 1000000
    int nb = (N + 1023) / 1024;

    int e_threads = (E + 3) / 4;
    int Ge = (e_threads + 255) / 256;        // 977 blocks for edge kernels

    deg_acc_kernel<<<Ge, 256>>>(ei, E);
    scan1_kernel<<<nb, 1024>>>(N);
    scan23_kernel<<<(N + 255) / 256, 256>>>(N, nb);
    fill_kernel<<<Ge, 256>>>(ei, E);
    gemm_mma_kernel<<<(N + TILE - 1) / TILE, 128>>>(x, W, N);
    gather_kernel<<<(N * 32 + 255) / 256, 256>>>(b, out, N);
}

// round 17
// speedup vs baseline: 1.0523x; 1.0474x over previous
#include <cuda_runtime.h>
#include <cuda_bf16.h>
#include <cuda_fp16.h>
#include <cstdint>

#define MAX_N 100000
#define MAX_E 1000000
#define D 64
#define TILE 64
#define PITCH 36

// Scratch (device globals: sanctioned alternative to cudaMalloc).
// INVARIANT: g_cnt is all-zero at kernel_launch entry (zero-initialized at
// module load; gather_kernel re-zeroes it after use every call).
__device__ __half g_hs[MAX_N * D];   // hs = dinv[n] * (x @ W^T)[n], fp16
__device__ float g_dinv[MAX_N];
__device__ int   g_cnt[MAX_N];
__device__ int   g_start[MAX_N];
__device__ int   g_cursor[MAX_N];
__device__ int   g_ebuf[MAX_E];
__device__ int   g_bsum[128];

// ---------------------------------------------------------------------------
// 1) degree histogram: 4 edges per thread (int4), fire-and-forget RED
// ---------------------------------------------------------------------------
__global__ void deg_acc_kernel(const int* __restrict__ ei, int E) {
    int e4 = (blockIdx.x * blockDim.x + threadIdx.x) * 4;
    if (e4 < E) {
        int4 d4 = *(const int4*)(ei + E + e4);
        asm volatile("red.global.add.s32 [%0], %1;" :: "l"(&g_cnt[d4.x]), "r"(1) : "memory");
        asm volatile("red.global.add.s32 [%0], %1;" :: "l"(&g_cnt[d4.y]), "r"(1) : "memory");
        asm volatile("red.global.add.s32 [%0], %1;" :: "l"(&g_cnt[d4.z]), "r"(1) : "memory");
        asm volatile("red.global.add.s32 [%0], %1;" :: "l"(&g_cnt[d4.w]), "r"(1) : "memory");
    }
}

// ---------------------------------------------------------------------------
// 2) level-1 scan
// ---------------------------------------------------------------------------
__global__ __launch_bounds__(1024)
void scan1_kernel(int N) {
    __shared__ int wsum[32];
    int i = blockIdx.x * 1024 + threadIdx.x;
    int lane = threadIdx.x & 31, wid = threadIdx.x >> 5;
    int v = (i < N) ? g_cnt[i] : 0;
    int val = v;
#pragma unroll
    for (int off = 1; off < 32; off <<= 1) {
        int t = __shfl_up_sync(0xffffffffu, val, off);
        if (lane >= off) val += t;
    }
    if (lane == 31) wsum[wid] = val;
    __syncthreads();
    if (wid == 0) {
        int w = wsum[lane];
#pragma unroll
        for (int off = 1; off < 32; off <<= 1) {
            int t = __shfl_up_sync(0xffffffffu, w, off);
            if (lane >= off) w += t;
        }
        wsum[lane] = w;
    }
    __syncthreads();
    int incl = val + (wid > 0 ? wsum[wid - 1] : 0);
    if (i < N) g_start[i] = incl - v;
    if (threadIdx.x == 1023) g_bsum[blockIdx.x] = incl;
}

// 3) fused level-2 scan + finalize (start/cursor/dinv)
__global__ __launch_bounds__(256)
void scan23_kernel(int N, int nb) {
    __shared__ int pre[128];
    int tid = threadIdx.x;
    if (tid < 32) {
        int run = 0;
        for (int b = 0; b < nb; b += 32) {
            int idx = b + tid;
            int v = (idx < nb) ? g_bsum[idx] : 0;
            int val = v;
#pragma unroll
            for (int off = 1; off < 32; off <<= 1) {
                int t = __shfl_up_sync(0xffffffffu, val, off);
                if (tid >= off) val += t;
            }
            if (idx < 128) pre[idx] = run + val - v;
            run += __shfl_sync(0xffffffffu, val, 31);
        }
    }
    __syncthreads();
    int i = blockIdx.x * 256 + tid;
    if (i < N) {
        int s = g_start[i] + pre[i >> 10];
        g_start[i]  = s;
        g_cursor[i] = s;
        g_dinv[i]   = rsqrtf(1.0f + (float)g_cnt[i]);
    }
}

// ---------------------------------------------------------------------------
// 4) bucket fill: 4 edges per thread (int4 loads, 4 independent atomic chains)
// ---------------------------------------------------------------------------
__global__ void fill_kernel(const int* __restrict__ ei, int E) {
    int e4 = (blockIdx.x * blockDim.x + threadIdx.x) * 4;
    if (e4 < E) {
        int4 d4 = *(const int4*)(ei + E + e4);   // dst first: start atomics ASAP
        int4 s4 = *(const int4*)(ei + e4);
        int p0 = atomicAdd(&g_cursor[d4.x], 1);
        int p1 = atomicAdd(&g_cursor[d4.y], 1);
        int p2 = atomicAdd(&g_cursor[d4.z], 1);
        int p3 = atomicAdd(&g_cursor[d4.w], 1);
        g_ebuf[p0] = s4.x;
        g_ebuf[p1] = s4.y;
        g_ebuf[p2] = s4.z;
        g_ebuf[p3] = s4.w;
    }
}

// ---------------------------------------------------------------------------
// Tensor-core GEMM via mma.sync (proven R12-R16): hs = dinv * (x @ W^T), fp16
// ---------------------------------------------------------------------------
__device__ __forceinline__ uint32_t pack_bf(float a, float b) {
    __nv_bfloat162 p = __floats2bfloat162_rn(a, b);
    return *(uint32_t*)&p;
}

#define MMA_BF16(c, a0, a1, a2, a3, b0, b1)                                   \
    asm volatile(                                                             \
        "mma.sync.aligned.m16n8k16.row.col.f32.bf16.bf16.f32 "                \
        "{%0,%1,%2,%3}, {%4,%5,%6,%7}, {%8,%9}, {%0,%1,%2,%3};"               \
        : "+f"((c)[0]), "+f"((c)[1]), "+f"((c)[2]), "+f"((c)[3])              \
        : "r"(a0), "r"(a1), "r"(a2), "r"(a3), "r"(b0), "r"(b1))

__global__ __launch_bounds__(128)
void gemm_mma_kernel(const float* __restrict__ x,
                     const float* __restrict__ W, int N) {
    __shared__ uint32_t Ah[TILE * PITCH], Al[TILE * PITCH];
    __shared__ uint32_t Bh[D * PITCH],   Bl[D * PITCH];

    int tid = threadIdx.x;
    int base = blockIdx.x * TILE;
    int rows = N - base; if (rows > TILE) rows = TILE;

    const float4* xg = (const float4*)(x + (size_t)base * D);
    for (int t = tid; t < rows * 16; t += 128) {
        int r = t >> 4, j = t & 15;
        float4 v = xg[t];
        float hx = __bfloat162float(__float2bfloat16(v.x));
        float hy = __bfloat162float(__float2bfloat16(v.y));
        float hz = __bfloat162float(__float2bfloat16(v.z));
        float hw = __bfloat162float(__float2bfloat16(v.w));
        Ah[r * PITCH + 2 * j]     = pack_bf(v.x, v.y);
        Ah[r * PITCH + 2 * j + 1] = pack_bf(v.z, v.w);
        Al[r * PITCH + 2 * j]     = pack_bf(v.x - hx, v.y - hy);
        Al[r * PITCH + 2 * j + 1] = pack_bf(v.z - hz, v.w - hw);
    }
    const float4* wg = (const float4*)W;
    for (int t = tid; t < D * 16; t += 128) {
        int o = t >> 4, j = t & 15;
        float4 v = wg[t];
        float hx = __bfloat162float(__float2bfloat16(v.x));
        float hy = __bfloat162float(__float2bfloat16(v.y));
        float hz = __bfloat162float(__float2bfloat16(v.z));
        float hw = __bfloat162float(__float2bfloat16(v.w));
        Bh[o * PITCH + 2 * j]     = pack_bf(v.x, v.y);
        Bh[o * PITCH + 2 * j + 1] = pack_bf(v.z, v.w);
        Bl[o * PITCH + 2 * j]     = pack_bf(v.x - hx, v.y - hy);
        Bl[o * PITCH + 2 * j + 1] = pack_bf(v.z - hz, v.w - hw);
    }
    __syncthreads();

    int lane = tid & 31;
    int w    = tid >> 5;
    int g    = lane >> 2;
    int kq   = lane & 3;
    int rb   = w * 16;

    float c[8][4];
#pragma unroll
    for (int t = 0; t < 8; t++)
#pragma unroll
        for (int i = 0; i < 4; i++) c[t][i] = 0.f;

#pragma unroll
    for (int s = 0; s < 4; s++) {
        int ko = s * 8 + kq;
        uint32_t ah0 = Ah[(rb + g) * PITCH + ko];
        uint32_t ah1 = Ah[(rb + g + 8) * PITCH + ko];
        uint32_t ah2 = Ah[(rb + g) * PITCH + ko + 4];
        uint32_t ah3 = Ah[(rb + g + 8) * PITCH + ko + 4];
        uint32_t al0 = Al[(rb + g) * PITCH + ko];
        uint32_t al1 = Al[(rb + g + 8) * PITCH + ko];
        uint32_t al2 = Al[(rb + g) * PITCH + ko + 4];
        uint32_t al3 = Al[(rb + g + 8) * PITCH + ko + 4];
#pragma unroll
        for (int t = 0; t < 8; t++) {
            int nr = t * 8 + g;
            uint32_t bh0 = Bh[nr * PITCH + ko];
            uint32_t bh1 = Bh[nr * PITCH + ko + 4];
            uint32_t bl0 = Bl[nr * PITCH + ko];
            uint32_t bl1 = Bl[nr * PITCH + ko + 4];
            MMA_BF16(c[t], ah0, ah1, ah2, ah3, bh0, bh1);
            MMA_BF16(c[t], ah0, ah1, ah2, ah3, bl0, bl1);
            MMA_BF16(c[t], al0, al1, al2, al3, bh0, bh1);
        }
    }

    int r0 = base + rb + g;
    int r1 = r0 + 8;
    bool v0 = (r0 < N), v1 = (r1 < N);
    float dv0 = v0 ? g_dinv[r0] : 0.f;
    float dv1 = v1 ? g_dinv[r1] : 0.f;

    __half2* h2 = (__half2*)g_hs;
#pragma unroll
    for (int t = 0; t < 8; t++) {
        int col2 = t * 4 + kq;
        if (v0) h2[(size_t)r0 * 32 + col2] =
            __floats2half2_rn(dv0 * c[t][0], dv0 * c[t][1]);
        if (v1) h2[(size_t)r1 * 32 + col2] =
            __floats2half2_rn(dv1 * c[t][2], dv1 * c[t][3]);
    }
}

// ---------------------------------------------------------------------------
// Gather: one warp per node; hs rows are fp16 (128B/row -> half the L2
// traffic of fp32). fp32 accumulation. Restores g_cnt invariant.
// ---------------------------------------------------------------------------
__global__ __launch_bounds__(256)
void gather_kernel(const float* __restrict__ bias,
                   float* __restrict__ out, int N) {
    int warp = (blockIdx.x * 256 + threadIdx.x) >> 5;
    int lane = threadIdx.x & 31;
    if (warp >= N) return;
    int n = warp;

    int start = g_start[n];
    int cnt   = g_cnt[n];

    const __half2* hs2 = (const __half2*)g_hs;

    float2 a0, a1, a2, a3;
    {
        float2 self = __half22float2(hs2[(size_t)n * 32 + lane]);
        a0 = self;
        a1 = make_float2(0.f, 0.f);
        a2 = make_float2(0.f, 0.f);
        a3 = make_float2(0.f, 0.f);
    }

    int i = 0;
    while (i < cnt) {
        int bc = cnt - i; if (bc > 32) bc = 32;
        int v = (lane < bc) ? g_ebuf[start + i + lane] : 0;
        int j = 0;
        for (; j + 4 <= bc; j += 4) {
            int s0 = __shfl_sync(0xffffffffu, v, j);
            int s1 = __shfl_sync(0xffffffffu, v, j + 1);
            int s2 = __shfl_sync(0xffffffffu, v, j + 2);
            int s3 = __shfl_sync(0xffffffffu, v, j + 3);
            float2 x0 = __half22float2(hs2[(size_t)s0 * 32 + lane]);
            float2 x1 = __half22float2(hs2[(size_t)s1 * 32 + lane]);
            float2 x2 = __half22float2(hs2[(size_t)s2 * 32 + lane]);
            float2 x3 = __half22float2(hs2[(size_t)s3 * 32 + lane]);
            a0.x += x0.x; a0.y += x0.y;
            a1.x += x1.x; a1.y += x1.y;
            a2.x += x2.x; a2.y += x2.y;
            a3.x += x3.x; a3.y += x3.y;
        }
        for (; j < bc; j++) {
            int s0 = __shfl_sync(0xffffffffu, v, j);
            float2 x0 = __half22float2(hs2[(size_t)s0 * 32 + lane]);
            a0.x += x0.x; a0.y += x0.y;
        }
        i += bc;
    }
    a0.x += (a1.x + a2.x) + a3.x;
    a0.y += (a1.y + a2.y) + a3.y;

    float dn = g_dinv[n];
    float2 bb = ((const float2*)bias)[lane];
    float2 o;
    o.x = fmaf(dn, a0.x, bb.x);
    o.y = fmaf(dn, a0.y, bb.y);
    ((float2*)out)[(size_t)n * 32 + lane] = o;

    if (lane == 0) g_cnt[n] = 0;   // restore invariant for next call
}

// ---------------------------------------------------------------------------
extern "C" void kernel_launch(void* const* d_in, const int* in_sizes, int n_in,
                              void* d_out, int out_size) {
    const float* x  = (const float*)d_in[0];
    const int*   ei = (const int*)d_in[1];
    const float* W  = (const float*)d_in[2];
    const float* b  = (const float*)d_in[3];
    float*       out = (float*)d_out;

    int N = in_sizes[0] / D;   // 100000
    int E = in_sizes[1] / 2;   // 1000000
    int nb = (N + 1023) / 1024;

    int e_threads = (E + 3) / 4;
    int Ge = (e_threads + 255) / 256;

    deg_acc_kernel<<<Ge, 256>>>(ei, E);
    scan1_kernel<<<nb, 1024>>>(N);
    scan23_kernel<<<(N + 255) / 256, 256>>>(N, nb);
    fill_kernel<<<Ge, 256>>>(ei, E);
    gemm_mma_kernel<<<(N + TILE - 1) / TILE, 128>>>(x, W, N);
    gather_kernel<<<(N * 32 + 255) / 256, 256>>>(b, out, N);
}